// round 3
// baseline (speedup 1.0000x reference)
#include <cuda_runtime.h>
#include <cstdint>
#include <cstddef>

#define T_STEPS 512
#define BATCH   64
#define DIN     128
#define DH      1024
#define DOUT    256
#define RNK     64

// Scratch for zi = x @ Wi^T  (static device global: allocation-free)
__device__ float g_zi[(size_t)T_STEPS * BATCH * DH];

// ---------------------------------------------------------------------------
// Generic fp32 GEMM:  C[M,N] = A[M,K] * B[N,K]^T (+ bias[n])   (unchanged)
// ---------------------------------------------------------------------------
#define BM 128
#define BN 64
#define BKK 16

__global__ __launch_bounds__(256) void gemm_nt_kernel(
    const float* __restrict__ A, const float* __restrict__ B,
    float* __restrict__ C, const float* __restrict__ bias,
    int M, int N, int K)
{
    __shared__ float As[BKK][BM + 4];
    __shared__ float Bs[BKK][BN + 4];

    const int tid = threadIdx.x;
    const int ty  = tid >> 4;
    const int tx  = tid & 15;

    const float* Ab = A + (size_t)blockIdx.x * BM * K;
    const float* Bb = B + (size_t)blockIdx.y * BN * K;

    float acc[8][4];
#pragma unroll
    for (int i = 0; i < 8; i++)
#pragma unroll
        for (int j = 0; j < 4; j++) acc[i][j] = 0.f;

    const int i0 = tid * 2, i1 = tid * 2 + 1;
    const int ar0 = i0 >> 2, ac0 = (i0 & 3) * 4;
    const int ar1 = i1 >> 2, ac1 = (i1 & 3) * 4;
    const int br  = tid >> 2, bc  = (tid & 3) * 4;

    float4 pa0 = *(const float4*)&Ab[(size_t)ar0 * K + ac0];
    float4 pa1 = *(const float4*)&Ab[(size_t)ar1 * K + ac1];
    float4 pb0 = *(const float4*)&Bb[(size_t)br  * K + bc];

    for (int kt = 0; kt < K; kt += BKK) {
        __syncthreads();
        As[ac0 + 0][ar0] = pa0.x; As[ac0 + 1][ar0] = pa0.y;
        As[ac0 + 2][ar0] = pa0.z; As[ac0 + 3][ar0] = pa0.w;
        As[ac1 + 0][ar1] = pa1.x; As[ac1 + 1][ar1] = pa1.y;
        As[ac1 + 2][ar1] = pa1.z; As[ac1 + 3][ar1] = pa1.w;
        Bs[bc  + 0][br ] = pb0.x; Bs[bc  + 1][br ] = pb0.y;
        Bs[bc  + 2][br ] = pb0.z; Bs[bc  + 3][br ] = pb0.w;
        __syncthreads();

        if (kt + BKK < K) {
            pa0 = *(const float4*)&Ab[(size_t)ar0 * K + kt + BKK + ac0];
            pa1 = *(const float4*)&Ab[(size_t)ar1 * K + kt + BKK + ac1];
            pb0 = *(const float4*)&Bb[(size_t)br  * K + kt + BKK + bc];
        }

#pragma unroll
        for (int k = 0; k < BKK; k++) {
            float ra[8], rb[4];
            *(float4*)&ra[0] = *(const float4*)&As[k][ty * 8];
            *(float4*)&ra[4] = *(const float4*)&As[k][ty * 8 + 4];
            *(float4*)&rb[0] = *(const float4*)&Bs[k][tx * 4];
#pragma unroll
            for (int i = 0; i < 8; i++)
#pragma unroll
                for (int j = 0; j < 4; j++)
                    acc[i][j] += ra[i] * rb[j];
        }
    }

    const int m0 = blockIdx.x * BM + ty * 8;
    const int n0 = blockIdx.y * BN + tx * 4;
    float bj0 = 0.f, bj1 = 0.f, bj2 = 0.f, bj3 = 0.f;
    if (bias) { bj0 = bias[n0]; bj1 = bias[n0 + 1]; bj2 = bias[n0 + 2]; bj3 = bias[n0 + 3]; }
#pragma unroll
    for (int i = 0; i < 8; i++) {
        float4 v = make_float4(acc[i][0] + bj0, acc[i][1] + bj1,
                               acc[i][2] + bj2, acc[i][3] + bj3);
        *(float4*)&C[(size_t)(m0 + i) * N + n0] = v;
    }
}

// ---------------------------------------------------------------------------
// Recurrence: 16 clusters x 8 CTAs, 4 batches/cluster, CTA owns 128 j.
// Reduce-free lane mappings, mbarrier push-signal cluster sync,
// cp.async double-buffered zi staging.
// ---------------------------------------------------------------------------
#define CLUSTER 8
#define SLICE   128
#define BPC     4
#define NTHR    256

// float offsets in dynamic smem
#define OFF_BAR 0                         // 2 x u64 mbarriers (4 floats)
#define OFF_V   4                         // 64 x 132
#define OFF_U   (OFF_V + 64 * 132)        // 128 x 68
#define OFF_H   (OFF_U + 128 * 68)        // 4 x 132   h[b][j]
#define OFF_ZI  (OFF_H + 4 * 132)         // 2 x 4 x 132 zi staging
#define OFF_P   (OFF_ZI + 2 * 4 * 132)    // 2 x 256   partial s, layout [r*4+b]
#define OFF_S   (OFF_P + 2 * 256)         // 4 x 68    s[b][r]
#define OFF_BH  (OFF_S + 4 * 68)          // 128
#define DYN_SMEM 122880                   // force 1 CTA/SM

__device__ __forceinline__ uint32_t smem_u32(const void* p) {
    return (uint32_t)__cvta_generic_to_shared(p);
}

__global__ void __cluster_dims__(CLUSTER, 1, 1) __launch_bounds__(NTHR, 1)
rnn_recurrence_kernel(const float* __restrict__ V, const float* __restrict__ U,
                      const float* __restrict__ bh, const float* __restrict__ zi,
                      float* __restrict__ hidden)
{
    extern __shared__ float sm[];
    float* V_s  = sm + OFF_V;
    float* U_s  = sm + OFF_U;
    float* h_s  = sm + OFF_H;
    float* zi_s = sm + OFF_ZI;
    float* part = sm + OFF_P;
    float* s_s  = sm + OFF_S;
    float* bh_s = sm + OFF_BH;

    const int tid = threadIdx.x;
    uint32_t rk;
    asm("mov.u32 %0, %%cluster_ctarank;" : "=r"(rk));
    const int bbase = (blockIdx.x / CLUSTER) * BPC;
    const int jbase = (int)rk * SLICE;

    // ---- weight / state loads (float4, padded rows kill bank conflicts) ----
    for (int i = tid; i < 2048; i += NTHR) {           // V slice 64x128
        int r = i >> 5, c = (i & 31) * 4;
        *(float4*)&V_s[r * 132 + c] = *(const float4*)&V[(size_t)r * DH + jbase + c];
    }
    for (int i = tid; i < 2048; i += NTHR) {           // U slice 128x64
        int j = i >> 4, c = (i & 15) * 4;
        *(float4*)&U_s[j * 68 + c] = *(const float4*)&U[(size_t)(jbase + j) * RNK + c];
    }
    if (tid < SLICE) bh_s[tid] = bh[jbase + tid];
    for (int i = tid; i < 4 * 132; i += NTHR) h_s[i] = 0.f;   // h0 = 0

    // ---- mbarrier init (count = 8 arrivals per phase) ----
    const uint32_t bar0 = smem_u32(sm + OFF_BAR);
    if (tid == 0) {
        asm volatile("mbarrier.init.shared.b64 [%0], %1;" :: "r"(bar0),     "r"(CLUSTER) : "memory");
        asm volatile("mbarrier.init.shared.b64 [%0], %1;" :: "r"(bar0 + 8), "r"(CLUSTER) : "memory");
    }
    __syncthreads();
    asm volatile("barrier.cluster.arrive.aligned;" ::: "memory");
    asm volatile("barrier.cluster.wait.aligned;"   ::: "memory");

    // ---- peer DSMEM base addresses of 'part' ----
    const uint32_t part_addr = smem_u32(part);
    uint32_t peer[CLUSTER];
#pragma unroll
    for (int p = 0; p < CLUSTER; p++)
        asm("mapa.shared::cluster.u32 %0, %1, %2;" : "=r"(peer[p]) : "r"(part_addr), "r"(p));

    const int lane = tid & 31, wid = tid >> 5;
    // GEMM1: lane = (b1, r_lo); thread -> s[b1][r1] over full local j
    const int b1 = lane & 3, r1 = wid * 8 + (lane >> 2);
    const float* vrow = &V_s[r1 * 132];
    const float* hrow = &h_s[b1 * 132];
    // GEMM2: lane = (b2, j_lo); thread -> h[b2][ja], h[b2][jb] over all 64 r
    const int b2 = lane >> 3, ja = wid * 8 + (lane & 7), jb = ja + 64;
    const float* ua   = &U_s[ja * 68];
    const float* ub   = &U_s[jb * 68];
    const float* srow = &s_s[b2 * 68];
    // pull-reduce mapping: tid <-> (r = tid>>2, b = tid&3)
    const int pr = tid >> 2, pb = tid & 3;
    // zi staging mapping
    const int zb = tid >> 5, zj = (tid & 31) * 4;

    // prime zi for t = 0
    if (tid < 128) {
        uint32_t dst = smem_u32(&zi_s[zb * 132 + zj]);
        const float* src = zi + (size_t)(bbase + zb) * DH + jbase + zj;
        asm volatile("cp.async.cg.shared.global [%0], [%1], 16;" :: "r"(dst), "l"(src) : "memory");
    }
    asm volatile("cp.async.commit_group;" ::: "memory");

    for (int t = 0; t < T_STEPS; t++) {
        const int buf = t & 1;
        const uint32_t par = (uint32_t)((t >> 1) & 1);

        // issue zi prefetch for t+1 into other buffer
        if (t + 1 < T_STEPS && tid < 128) {
            uint32_t dst = smem_u32(&zi_s[(buf ^ 1) * 528 + zb * 132 + zj]);
            const float* src = zi + (size_t)((t + 1) * BATCH + bbase + zb) * DH + jbase + zj;
            asm volatile("cp.async.cg.shared.global [%0], [%1], 16;" :: "r"(dst), "l"(src) : "memory");
        }
        asm volatile("cp.async.commit_group;" ::: "memory");

        // ---- GEMM1: s_part[b1][r1] = sum_j h[b1][j] * V[r1][j] ----
        float4 a = make_float4(0.f, 0.f, 0.f, 0.f);
#pragma unroll
        for (int jj = 0; jj < 32; jj++) {
            float4 v = *(const float4*)&vrow[jj * 4];
            float4 h = *(const float4*)&hrow[jj * 4];
            a.x += v.x * h.x; a.y += v.y * h.y;
            a.z += v.z * h.z; a.w += v.w * h.w;
        }
        part[buf * 256 + r1 * 4 + b1] = (a.x + a.y) + (a.z + a.w);
        __syncthreads();

        // ---- push-signal: arrive on every peer's bar[buf] ----
        if (tid < CLUSTER) {
            uint32_t rem;
            asm("mapa.shared::cluster.u32 %0, %1, %2;"
                : "=r"(rem) : "r"(bar0 + buf * 8), "r"(tid));
            asm volatile("mbarrier.arrive.release.cluster.shared::cluster.b64 _, [%0];"
                         :: "r"(rem) : "memory");
        }
        // wait for all 8 CTAs' arrivals
        asm volatile(
            "{\n\t.reg .pred P;\n\t"
            "RNNWAIT_%=:\n\t"
            "mbarrier.try_wait.parity.acquire.cluster.shared::cta.b64 P, [%0], %1, 0x989680;\n\t"
            "@!P bra RNNWAIT_%=;\n\t"
            "}"
            :: "r"(bar0 + buf * 8), "r"(par) : "memory");

        // ---- pull-reduce s across 8 CTAs (1KB each) ----
        {
            float ssum = 0.f;
            const uint32_t off = (uint32_t)((buf * 256 + tid) * 4);
#pragma unroll
            for (int p = 0; p < CLUSTER; p++) {
                float v;
                asm volatile("ld.shared::cluster.f32 %0, [%1];"
                             : "=f"(v) : "r"(peer[p] + off));
                ssum += v;
            }
            s_s[pb * 68 + pr] = ssum;
        }
        asm volatile("cp.async.wait_group 1;" ::: "memory");
        __syncthreads();

        // ---- GEMM2: h[b2][j] = relu(sum_r s[b2][r]*U[j][r] + bh + zi) ----
        float4 aa = make_float4(0.f, 0.f, 0.f, 0.f);
        float4 ab = make_float4(0.f, 0.f, 0.f, 0.f);
#pragma unroll
        for (int rr = 0; rr < 16; rr++) {
            float4 s4  = *(const float4*)&srow[rr * 4];
            float4 u4a = *(const float4*)&ua[rr * 4];
            float4 u4b = *(const float4*)&ub[rr * 4];
            aa.x += u4a.x * s4.x; aa.y += u4a.y * s4.y;
            aa.z += u4a.z * s4.z; aa.w += u4a.w * s4.w;
            ab.x += u4b.x * s4.x; ab.y += u4b.y * s4.y;
            ab.z += u4b.z * s4.z; ab.w += u4b.w * s4.w;
        }
        {
            float sa  = (aa.x + aa.y) + (aa.z + aa.w);
            float sb  = (ab.x + ab.y) + (ab.z + ab.w);
            float za  = zi_s[buf * 528 + b2 * 132 + ja];
            float zb2 = zi_s[buf * 528 + b2 * 132 + jb];
            float ha = fmaxf(sa + bh_s[ja] + za,  0.f);
            float hb = fmaxf(sb + bh_s[jb] + zb2, 0.f);
            h_s[b2 * 132 + ja] = ha;
            h_s[b2 * 132 + jb] = hb;
            float* hp = hidden + (size_t)(t * BATCH + bbase + b2) * DH + jbase;
            hp[ja] = ha; hp[jb] = hb;
        }
        __syncthreads();   // h_s visible for next step's GEMM1
    }

    // keep smem alive until all peers are done pulling
    asm volatile("barrier.cluster.arrive.aligned;" ::: "memory");
    asm volatile("barrier.cluster.wait.aligned;"   ::: "memory");
}

// ---------------------------------------------------------------------------
extern "C" void kernel_launch(void* const* d_in, const int* in_sizes, int n_in,
                              void* d_out, int out_size)
{
    const float* x  = (const float*)d_in[0];
    const float* Wi = (const float*)d_in[1];
    const float* U  = (const float*)d_in[2];
    const float* V  = (const float*)d_in[3];
    const float* bh = (const float*)d_in[4];
    const float* Wo = (const float*)d_in[5];
    const float* bo = (const float*)d_in[6];

    float* hidden = (float*)d_out;                                    // [T,B,DH]
    float* output = (float*)d_out + (size_t)T_STEPS * BATCH * DH;     // [T,B,DOUT]

    float* zi = nullptr;
    cudaGetSymbolAddress((void**)&zi, g_zi);

    cudaFuncSetAttribute(rnn_recurrence_kernel,
                         cudaFuncAttributeMaxDynamicSharedMemorySize, DYN_SMEM);

    // K1: zi = x @ Wi^T    (M=32768, N=1024, K=128)
    {
        dim3 grid(T_STEPS * BATCH / BM, DH / BN);
        gemm_nt_kernel<<<grid, 256>>>(x, Wi, zi, nullptr,
                                      T_STEPS * BATCH, DH, DIN);
    }

    // K2: recurrence (writes hidden)
    {
        rnn_recurrence_kernel<<<128, NTHR, DYN_SMEM>>>(V, U, bh, zi, hidden);
    }

    // K3: output = hidden @ Wo^T + bo   (M=32768, N=256, K=1024)
    {
        dim3 grid(T_STEPS * BATCH / BM, DOUT / BN);
        gemm_nt_kernel<<<grid, 256>>>(hidden, Wo, output, bo,
                                      T_STEPS * BATCH, DOUT, DH);
    }
}

// round 12
// speedup vs baseline: 1.2182x; 1.2182x over previous
#include <cuda_runtime.h>
#include <cstdint>
#include <cstddef>

#define T_STEPS 512
#define BATCH   64
#define DIN     128
#define DH      1024
#define DOUT    256
#define RNK     64

// Scratch for zi = x @ Wi^T  (static device global: allocation-free)
__device__ float g_zi[(size_t)T_STEPS * BATCH * DH];

// ---------------------------------------------------------------------------
// Generic fp32 GEMM:  C[M,N] = A[M,K] * B[N,K]^T (+ bias[n])   (unchanged)
// ---------------------------------------------------------------------------
#define BM 128
#define BN 64
#define BKK 16

__global__ __launch_bounds__(256) void gemm_nt_kernel(
    const float* __restrict__ A, const float* __restrict__ B,
    float* __restrict__ C, const float* __restrict__ bias,
    int M, int N, int K)
{
    __shared__ float As[BKK][BM + 4];
    __shared__ float Bs[BKK][BN + 4];

    const int tid = threadIdx.x;
    const int ty  = tid >> 4;
    const int tx  = tid & 15;

    const float* Ab = A + (size_t)blockIdx.x * BM * K;
    const float* Bb = B + (size_t)blockIdx.y * BN * K;

    float acc[8][4];
#pragma unroll
    for (int i = 0; i < 8; i++)
#pragma unroll
        for (int j = 0; j < 4; j++) acc[i][j] = 0.f;

    const int i0 = tid * 2, i1 = tid * 2 + 1;
    const int ar0 = i0 >> 2, ac0 = (i0 & 3) * 4;
    const int ar1 = i1 >> 2, ac1 = (i1 & 3) * 4;
    const int br  = tid >> 2, bc  = (tid & 3) * 4;

    float4 pa0 = *(const float4*)&Ab[(size_t)ar0 * K + ac0];
    float4 pa1 = *(const float4*)&Ab[(size_t)ar1 * K + ac1];
    float4 pb0 = *(const float4*)&Bb[(size_t)br  * K + bc];

    for (int kt = 0; kt < K; kt += BKK) {
        __syncthreads();
        As[ac0 + 0][ar0] = pa0.x; As[ac0 + 1][ar0] = pa0.y;
        As[ac0 + 2][ar0] = pa0.z; As[ac0 + 3][ar0] = pa0.w;
        As[ac1 + 0][ar1] = pa1.x; As[ac1 + 1][ar1] = pa1.y;
        As[ac1 + 2][ar1] = pa1.z; As[ac1 + 3][ar1] = pa1.w;
        Bs[bc  + 0][br ] = pb0.x; Bs[bc  + 1][br ] = pb0.y;
        Bs[bc  + 2][br ] = pb0.z; Bs[bc  + 3][br ] = pb0.w;
        __syncthreads();

        if (kt + BKK < K) {
            pa0 = *(const float4*)&Ab[(size_t)ar0 * K + kt + BKK + ac0];
            pa1 = *(const float4*)&Ab[(size_t)ar1 * K + kt + BKK + ac1];
            pb0 = *(const float4*)&Bb[(size_t)br  * K + kt + BKK + bc];
        }

#pragma unroll
        for (int k = 0; k < BKK; k++) {
            float ra[8], rb[4];
            *(float4*)&ra[0] = *(const float4*)&As[k][ty * 8];
            *(float4*)&ra[4] = *(const float4*)&As[k][ty * 8 + 4];
            *(float4*)&rb[0] = *(const float4*)&Bs[k][tx * 4];
#pragma unroll
            for (int i = 0; i < 8; i++)
#pragma unroll
                for (int j = 0; j < 4; j++)
                    acc[i][j] += ra[i] * rb[j];
        }
    }

    const int m0 = blockIdx.x * BM + ty * 8;
    const int n0 = blockIdx.y * BN + tx * 4;
    float bj0 = 0.f, bj1 = 0.f, bj2 = 0.f, bj3 = 0.f;
    if (bias) { bj0 = bias[n0]; bj1 = bias[n0 + 1]; bj2 = bias[n0 + 2]; bj3 = bias[n0 + 3]; }
#pragma unroll
    for (int i = 0; i < 8; i++) {
        float4 v = make_float4(acc[i][0] + bj0, acc[i][1] + bj1,
                               acc[i][2] + bj2, acc[i][3] + bj3);
        *(float4*)&C[(size_t)(m0 + i) * N + n0] = v;
    }
}

// ---------------------------------------------------------------------------
// Recurrence: 16 clusters x 8 CTAs, 4 batches/cluster, CTA owns 128 j.
// barrier.cluster sync (R1-proven), f32x2 packed FMA, U register-resident,
// reduce-free lane mappings, cp.async double-buffered zi staging.
// ---------------------------------------------------------------------------
#define CLUSTER 8
#define SLICE   128
#define BPC     4
#define NTHR    256

// float offsets in dynamic smem
#define OFF_V   4                         // 64 x 132
#define OFF_H   (OFF_V + 64 * 132)        // 4 x 132   h[b][j]
#define OFF_ZI  (OFF_H + 4 * 132)         // 2 x 4 x 132 zi staging
#define OFF_P   (OFF_ZI + 2 * 4 * 132)    // 2 x 256   partial s, layout [r*4+b]
#define OFF_S   (OFF_P + 2 * 256)         // 4 x 68    s[b][r]
#define OFF_BH  (OFF_S + 4 * 68)          // 128
#define DYN_SMEM 122880                   // force 1 CTA/SM

typedef unsigned long long u64t;

#define FFMA2(d, a, b, c) \
    asm("fma.rn.f32x2 %0, %1, %2, %3;" : "=l"(d) : "l"(a), "l"(b), "l"(c))
#define PACK2(d, lo, hi) \
    asm("mov.b64 %0, {%1, %2};" : "=l"(d) : "f"(lo), "f"(hi))
#define UNPACK2(lo, hi, s) \
    asm("mov.b64 {%0, %1}, %2;" : "=f"(lo), "=f"(hi) : "l"(s))

__device__ __forceinline__ uint32_t smem_u32(const void* p) {
    return (uint32_t)__cvta_generic_to_shared(p);
}

__global__ void __cluster_dims__(CLUSTER, 1, 1) __launch_bounds__(NTHR, 1)
rnn_recurrence_kernel(const float* __restrict__ V, const float* __restrict__ U,
                      const float* __restrict__ bh, const float* __restrict__ zi,
                      float* __restrict__ hidden)
{
    extern __shared__ float sm[];
    float* V_s  = sm + OFF_V;
    float* h_s  = sm + OFF_H;
    float* zi_s = sm + OFF_ZI;
    float* part = sm + OFF_P;
    float* s_s  = sm + OFF_S;
    float* bh_s = sm + OFF_BH;

    const int tid = threadIdx.x;
    uint32_t rk;
    asm("mov.u32 %0, %%cluster_ctarank;" : "=r"(rk));
    const int bbase = (blockIdx.x / CLUSTER) * BPC;
    const int jbase = (int)rk * SLICE;

    // ---- V slice into SMEM (padded rows) ----
    for (int i = tid; i < 2048; i += NTHR) {
        int r = i >> 5, c = (i & 31) * 4;
        *(float4*)&V_s[r * 132 + c] = *(const float4*)&V[(size_t)r * DH + jbase + c];
    }
    if (tid < SLICE) bh_s[tid] = bh[jbase + tid];
    for (int i = tid; i < 4 * 132; i += NTHR) h_s[i] = 0.f;   // h0 = 0

    const int lane = tid & 31, wid = tid >> 5;
    // GEMM1: thread -> s[b1][r1] over full local j
    const int b1 = lane & 3, r1 = wid * 8 + (lane >> 2);
    const float* vrow = &V_s[r1 * 132];
    const float* hrow = &h_s[b1 * 132];
    // GEMM2: thread -> h[b2][ja], h[b2][jb] over all 64 r
    const int b2 = lane >> 3, ja = wid * 8 + (lane & 7), jb = ja + 64;
    const float* srow = &s_s[b2 * 68];
    // pull-reduce mapping: tid <-> (r = tid>>2, b = tid&3)
    const int pr = tid >> 2, pb = tid & 3;
    // zi staging mapping
    const int zb = tid >> 5, zj = (tid & 31) * 4;

    // ---- U rows register-resident (fixed across all 512 steps) ----
    u64t Ua[32], Ub[32];
    {
        const float* Uj = U + (size_t)(jbase + ja) * RNK;
#pragma unroll
        for (int i = 0; i < 32; i++) {
            float2 f = *(const float2*)(Uj + 2 * i);
            PACK2(Ua[i], f.x, f.y);
        }
        Uj = U + (size_t)(jbase + jb) * RNK;
#pragma unroll
        for (int i = 0; i < 32; i++) {
            float2 f = *(const float2*)(Uj + 2 * i);
            PACK2(Ub[i], f.x, f.y);
        }
    }

    // ---- peer DSMEM base addresses of 'part' ----
    const uint32_t part_addr = smem_u32(part);
    uint32_t peer[CLUSTER];
#pragma unroll
    for (int p = 0; p < CLUSTER; p++)
        asm("mapa.shared::cluster.u32 %0, %1, %2;" : "=r"(peer[p]) : "r"(part_addr), "r"(p));

    __syncthreads();

    // prime zi for t = 0
    if (tid < 128) {
        uint32_t dst = smem_u32(&zi_s[zb * 132 + zj]);
        const float* src = zi + (size_t)(bbase + zb) * DH + jbase + zj;
        asm volatile("cp.async.cg.shared.global [%0], [%1], 16;" :: "r"(dst), "l"(src) : "memory");
    }
    asm volatile("cp.async.commit_group;" ::: "memory");

    for (int t = 0; t < T_STEPS; t++) {
        const int buf = t & 1;

        // issue zi prefetch for t+1 into other buffer
        if (t + 1 < T_STEPS && tid < 128) {
            uint32_t dst = smem_u32(&zi_s[(buf ^ 1) * 528 + zb * 132 + zj]);
            const float* src = zi + (size_t)((t + 1) * BATCH + bbase + zb) * DH + jbase + zj;
            asm volatile("cp.async.cg.shared.global [%0], [%1], 16;" :: "r"(dst), "l"(src) : "memory");
        }
        asm volatile("cp.async.commit_group;" ::: "memory");

        // ---- GEMM1: s_part[b1][r1] = sum_j h[b1][j] * V[r1][j]  (f32x2) ----
        {
            u64t accP, accQ;
            PACK2(accP, 0.f, 0.f);
            PACK2(accQ, 0.f, 0.f);
#pragma unroll
            for (int jj = 0; jj < 32; jj++) {
                ulonglong2 v2 = *(const ulonglong2*)&vrow[jj * 4];
                ulonglong2 h2 = *(const ulonglong2*)&hrow[jj * 4];
                FFMA2(accP, v2.x, h2.x, accP);
                FFMA2(accQ, v2.y, h2.y, accQ);
            }
            float p0, p1, q0, q1;
            UNPACK2(p0, p1, accP);
            UNPACK2(q0, q1, accQ);
            part[buf * 256 + r1 * 4 + b1] = (p0 + p1) + (q0 + q1);
        }

        // ---- cluster barrier (full CTA + cluster barrier; release/acquire) ----
        asm volatile("barrier.cluster.arrive.aligned;" ::: "memory");
        asm volatile("barrier.cluster.wait.aligned;"   ::: "memory");

        // ---- pull-reduce s across 8 CTAs (1KB each) ----
        {
            float ssum = 0.f;
            const uint32_t off = (uint32_t)((buf * 256 + tid) * 4);
#pragma unroll
            for (int p = 0; p < CLUSTER; p++) {
                float v;
                asm volatile("ld.shared::cluster.f32 %0, [%1];"
                             : "=f"(v) : "r"(peer[p] + off));
                ssum += v;
            }
            s_s[pb * 68 + pr] = ssum;
        }
        asm volatile("cp.async.wait_group 1;" ::: "memory");
        __syncthreads();

        // ---- GEMM2: h[b][j] = relu(sum_r s[b][r]*U[j][r] + bh + zi)  (f32x2) ----
        {
            u64t aP, aQ, bP, bQ;
            PACK2(aP, 0.f, 0.f); PACK2(aQ, 0.f, 0.f);
            PACK2(bP, 0.f, 0.f); PACK2(bQ, 0.f, 0.f);
#pragma unroll
            for (int rr = 0; rr < 16; rr++) {
                ulonglong2 s2 = *(const ulonglong2*)&srow[rr * 4];
                FFMA2(aP, Ua[2 * rr],     s2.x, aP);
                FFMA2(aQ, Ua[2 * rr + 1], s2.y, aQ);
                FFMA2(bP, Ub[2 * rr],     s2.x, bP);
                FFMA2(bQ, Ub[2 * rr + 1], s2.y, bQ);
            }
            float x0, x1, y0, y1;
            UNPACK2(x0, x1, aP); UNPACK2(y0, y1, aQ);
            float sa = (x0 + x1) + (y0 + y1);
            UNPACK2(x0, x1, bP); UNPACK2(y0, y1, bQ);
            float sb = (x0 + x1) + (y0 + y1);

            float za  = zi_s[buf * 528 + b2 * 132 + ja];
            float zb2 = zi_s[buf * 528 + b2 * 132 + jb];
            float ha = fmaxf(sa + bh_s[ja] + za,  0.f);
            float hb = fmaxf(sb + bh_s[jb] + zb2, 0.f);
            h_s[b2 * 132 + ja] = ha;
            h_s[b2 * 132 + jb] = hb;
            float* hp = hidden + (size_t)(t * BATCH + bbase + b2) * DH + jbase;
            hp[ja] = ha; hp[jb] = hb;
        }
        __syncthreads();   // h_s visible for next step's GEMM1
    }

    // keep smem alive until all peers are done pulling
    asm volatile("barrier.cluster.arrive.aligned;" ::: "memory");
    asm volatile("barrier.cluster.wait.aligned;"   ::: "memory");
}

// ---------------------------------------------------------------------------
extern "C" void kernel_launch(void* const* d_in, const int* in_sizes, int n_in,
                              void* d_out, int out_size)
{
    const float* x  = (const float*)d_in[0];
    const float* Wi = (const float*)d_in[1];
    const float* U  = (const float*)d_in[2];
    const float* V  = (const float*)d_in[3];
    const float* bh = (const float*)d_in[4];
    const float* Wo = (const float*)d_in[5];
    const float* bo = (const float*)d_in[6];

    float* hidden = (float*)d_out;                                    // [T,B,DH]
    float* output = (float*)d_out + (size_t)T_STEPS * BATCH * DH;     // [T,B,DOUT]

    float* zi = nullptr;
    cudaGetSymbolAddress((void**)&zi, g_zi);

    cudaFuncSetAttribute(rnn_recurrence_kernel,
                         cudaFuncAttributeMaxDynamicSharedMemorySize, DYN_SMEM);

    // K1: zi = x @ Wi^T    (M=32768, N=1024, K=128)
    {
        dim3 grid(T_STEPS * BATCH / BM, DH / BN);
        gemm_nt_kernel<<<grid, 256>>>(x, Wi, zi, nullptr,
                                      T_STEPS * BATCH, DH, DIN);
    }

    // K2: recurrence (writes hidden)
    {
        rnn_recurrence_kernel<<<128, NTHR, DYN_SMEM>>>(V, U, bh, zi, hidden);
    }

    // K3: output = hidden @ Wo^T + bo   (M=32768, N=256, K=1024)
    {
        dim3 grid(T_STEPS * BATCH / BM, DOUT / BN);
        gemm_nt_kernel<<<grid, 256>>>(hidden, Wo, output, bo,
                                      T_STEPS * BATCH, DOUT, DH);
    }
}